// round 1
// baseline (speedup 1.0000x reference)
#include <cuda_runtime.h>
#include <cstdint>

// DotReluAttention: out = relu(Q @ K^T / D) @ V
// B=2, H=8, S=4096, D=64, fp32 in/out.
// Fused two-GEMM kernel using mma.sync.m16n8k8 tf32.

#define BHEADS 16      // B*H
#define SEQ    4096
#define HD     64      // head dim
#define BM     128     // q rows per CTA
#define BN     64      // kv rows per iteration
#define NTHREADS 256   // 8 warps, each owns 16 q rows

// smem strides (in 32-bit words) chosen for conflict-free fragment access
#define SK 68   // K tile stride   (4*gid + tig distinct mod 32)
#define SV 72   // V tile stride   (8*tig + gid distinct mod 32)
#define SP 68   // P tile / Q staging stride

#define SMEM_WORDS (BM*SP + BN*SK + BN*SV)
#define SMEM_BYTES (SMEM_WORDS * 4)

__device__ __forceinline__ uint32_t f2tf32(float f) {
    uint32_t r;
    asm("cvt.rna.tf32.f32 %0, %1;" : "=r"(r) : "f"(f));
    return r;
}

__device__ __forceinline__ void mma_tf32(float* c, const uint32_t* a,
                                         uint32_t b0, uint32_t b1) {
    asm volatile(
        "mma.sync.aligned.m16n8k8.row.col.f32.tf32.tf32.f32 "
        "{%0,%1,%2,%3}, {%4,%5,%6,%7}, {%8,%9}, {%0,%1,%2,%3};\n"
        : "+f"(c[0]), "+f"(c[1]), "+f"(c[2]), "+f"(c[3])
        : "r"(a[0]), "r"(a[1]), "r"(a[2]), "r"(a[3]), "r"(b0), "r"(b1));
}

__global__ __launch_bounds__(NTHREADS)
void dot_relu_attn_kernel(const float* __restrict__ Q,
                          const float* __restrict__ K,
                          const float* __restrict__ V,
                          float* __restrict__ O) {
    extern __shared__ uint32_t smem[];
    uint32_t* sP = smem;                 // [BM][SP]  P tile (also Q staging)
    uint32_t* sK = sP + BM * SP;         // [BN][SK]
    uint32_t* sV = sK + BN * SK;         // [BN][SV]

    const int bh    = blockIdx.y;
    const int qbase = blockIdx.x * BM;

    const float* Qp = Q + ((size_t)bh * SEQ + qbase) * HD;
    const float* Kp = K + (size_t)bh * SEQ * HD;
    const float* Vp = V + (size_t)bh * SEQ * HD;
    float*       Op = O + ((size_t)bh * SEQ + qbase) * HD;

    const int tid  = threadIdx.x;
    const int warp = tid >> 5;
    const int lane = tid & 31;
    const int gid  = lane >> 2;   // groupID  (0..7)
    const int tig  = lane & 3;    // thread-in-group (0..3)
    const int m0   = warp * 16;   // this warp's q-row base within the tile

    // ---- Stage Q tile (BM x HD) into smem (tf32), then pull A fragments ----
    #pragma unroll
    for (int i = 0; i < 8; i++) {
        int idx = tid + i * NTHREADS;     // float4 index (2048 total)
        int row = idx >> 4;               // 16 float4 per row
        int c4  = idx & 15;
        float4 v = *reinterpret_cast<const float4*>(Qp + row * HD + c4 * 4);
        uint32_t* dst = &sP[row * SP + c4 * 4];
        dst[0] = f2tf32(v.x); dst[1] = f2tf32(v.y);
        dst[2] = f2tf32(v.z); dst[3] = f2tf32(v.w);
    }
    __syncthreads();

    uint32_t qa[8][4];   // Q A-fragments: 8 k-tiles over HD=64
    #pragma unroll
    for (int kt = 0; kt < 8; kt++) {
        int c = kt * 8 + tig;
        qa[kt][0] = sP[(m0 + gid)     * SP + c];
        qa[kt][1] = sP[(m0 + gid + 8) * SP + c];
        qa[kt][2] = sP[(m0 + gid)     * SP + c + 4];
        qa[kt][3] = sP[(m0 + gid + 8) * SP + c + 4];
    }
    __syncthreads();   // staging done; sP now free for P tiles

    float oacc[8][4];    // O accumulator: 16 x 64 per warp
    #pragma unroll
    for (int i = 0; i < 8; i++)
        #pragma unroll
        for (int j = 0; j < 4; j++) oacc[i][j] = 0.f;

    for (int kv = 0; kv < SEQ; kv += BN) {
        // ---- Load K,V tiles (BN x HD each) into smem, converting to tf32 ----
        #pragma unroll
        for (int i = 0; i < 4; i++) {
            int idx = tid + i * NTHREADS;   // float4 index (1024 total)
            int row = idx >> 4;
            int c4  = idx & 15;
            float4 kq = *reinterpret_cast<const float4*>(Kp + (kv + row) * HD + c4 * 4);
            uint32_t* dk = &sK[row * SK + c4 * 4];
            dk[0] = f2tf32(kq.x); dk[1] = f2tf32(kq.y);
            dk[2] = f2tf32(kq.z); dk[3] = f2tf32(kq.w);
            float4 vq = *reinterpret_cast<const float4*>(Vp + (kv + row) * HD + c4 * 4);
            uint32_t* dv = &sV[row * SV + c4 * 4];
            dv[0] = f2tf32(vq.x); dv[1] = f2tf32(vq.y);
            dv[2] = f2tf32(vq.z); dv[3] = f2tf32(vq.w);
        }
        __syncthreads();

        // ---- GEMM1: S = Q @ K^T   (per warp: 16 x BN, k over HD) ----
        float sacc[8][4];
        #pragma unroll
        for (int i = 0; i < 8; i++) {
            sacc[i][0] = 0.f; sacc[i][1] = 0.f; sacc[i][2] = 0.f; sacc[i][3] = 0.f;
        }
        #pragma unroll
        for (int kt = 0; kt < 8; kt++) {
            #pragma unroll
            for (int nt = 0; nt < 8; nt++) {
                // B[k][n] = K[n][k]; n = nt*8+gid, k = kt*8+tig (+4)
                uint32_t b0 = sK[(nt * 8 + gid) * SK + kt * 8 + tig];
                uint32_t b1 = sK[(nt * 8 + gid) * SK + kt * 8 + tig + 4];
                mma_tf32(sacc[nt], qa[kt], b0, b1);
            }
        }

        // ---- relu(S/64), write P tile (own rows only -> no barrier needed) ----
        #pragma unroll
        for (int nt = 0; nt < 8; nt++) {
            int col = nt * 8 + 2 * tig;
            sP[(m0 + gid)     * SP + col]     = f2tf32(fmaxf(sacc[nt][0] * (1.f/64.f), 0.f));
            sP[(m0 + gid)     * SP + col + 1] = f2tf32(fmaxf(sacc[nt][1] * (1.f/64.f), 0.f));
            sP[(m0 + gid + 8) * SP + col]     = f2tf32(fmaxf(sacc[nt][2] * (1.f/64.f), 0.f));
            sP[(m0 + gid + 8) * SP + col + 1] = f2tf32(fmaxf(sacc[nt][3] * (1.f/64.f), 0.f));
        }
        // same-warp smem write->read: program order suffices, no __syncthreads

        // ---- GEMM2: O += P @ V   (per warp: 16 x HD, k over BN) ----
        #pragma unroll
        for (int kt = 0; kt < 8; kt++) {
            uint32_t pa[4];
            int c = kt * 8 + tig;
            pa[0] = sP[(m0 + gid)     * SP + c];
            pa[1] = sP[(m0 + gid + 8) * SP + c];
            pa[2] = sP[(m0 + gid)     * SP + c + 4];
            pa[3] = sP[(m0 + gid + 8) * SP + c + 4];
            #pragma unroll
            for (int nt = 0; nt < 8; nt++) {
                // B[k][n] = V[k][n]; k = kt*8+tig (+4), n = nt*8+gid
                uint32_t b0 = sV[(kt * 8 + tig)     * SV + nt * 8 + gid];
                uint32_t b1 = sV[(kt * 8 + tig + 4) * SV + nt * 8 + gid];
                mma_tf32(oacc[nt], pa, b0, b1);
            }
        }
        __syncthreads();   // all reads of sK/sV done before next tile load
    }

    // ---- Epilogue: write O (each warp owns 16 full rows) ----
    #pragma unroll
    for (int nt = 0; nt < 8; nt++) {
        int col = nt * 8 + 2 * tig;
        float2 v0 = make_float2(oacc[nt][0], oacc[nt][1]);
        float2 v1 = make_float2(oacc[nt][2], oacc[nt][3]);
        *reinterpret_cast<float2*>(Op + (m0 + gid)     * HD + col) = v0;
        *reinterpret_cast<float2*>(Op + (m0 + gid + 8) * HD + col) = v1;
    }
}

extern "C" void kernel_launch(void* const* d_in, const int* in_sizes, int n_in,
                              void* d_out, int out_size) {
    const float* q = (const float*)d_in[0];
    const float* k = (const float*)d_in[1];
    const float* v = (const float*)d_in[2];
    float* o = (float*)d_out;

    // > 48KB static limit, so use dynamic smem (idempotent attribute set)
    cudaFuncSetAttribute(dot_relu_attn_kernel,
                         cudaFuncAttributeMaxDynamicSharedMemorySize, SMEM_BYTES);

    dim3 grid(SEQ / BM, BHEADS);
    dot_relu_attn_kernel<<<grid, NTHREADS, SMEM_BYTES>>>(q, k, v, o);
}